// round 1
// baseline (speedup 1.0000x reference)
#include <cuda_runtime.h>
#include <cuda_bf16.h>
#include <cstdint>

// KernelDensityEstimate: prob[n,m] = (sum_q exp(-0.5*inv_var*||a_n - b_{m,q}||^2))
//                                    / (sum_m' dens[n,m'] + 1e-10)
// Key insight: with var=0.5 and N(0,1) data, ||a-b||^2 ~ 256 +- 32, and fp32
// exp underflows below -103.97 => essentially every density is exactly 0 in the
// fp32 reference. We therefore SCREEN with a bf16 tensor-core GEMM (worst-case
// exponent error <= ~2.7, bounded) and only recompute exactly (fp32 dot + expf)
// for entries with screened exponent > -115. That branch is ~never taken.

#define N_ROWS 4096
#define M_CL   128
#define Q_PTS  64
#define D_DIM  128
#define MQ     (M_CL * Q_PTS)

#define SA 136   // padded bf16 row stride for A tile (conflict-free frag loads)
#define SB 136   // padded bf16 row stride for B tile

// Scratch (allocation-free rule: __device__ globals)
__device__ __nv_bfloat16 g_Abf[N_ROWS * D_DIM];
__device__ __nv_bfloat16 g_Bbf[MQ * D_DIM];
__device__ float g_a2[N_ROWS];
__device__ float g_b2[MQ];
__device__ float g_dens[N_ROWS * M_CL];

__device__ __forceinline__ float warp_sum(float v) {
#pragma unroll
    for (int o = 16; o > 0; o >>= 1) v += __shfl_xor_sync(0xffffffffu, v, o);
    return v;
}

// ---------------------------------------------------------------------------
// Prep: convert to bf16 and compute row squared norms.
// ---------------------------------------------------------------------------
__global__ void prep_a_kernel(const float* __restrict__ A) {
    int row = blockIdx.x, t = threadIdx.x;               // 128 threads = D
    float v = A[row * D_DIM + t];
    g_Abf[row * D_DIM + t] = __float2bfloat16(v);
    float s = warp_sum(v * v);
    __shared__ float sm[4];
    if ((t & 31) == 0) sm[t >> 5] = s;
    __syncthreads();
    if (t == 0) g_a2[row] = sm[0] + sm[1] + sm[2] + sm[3];
}

__global__ void prep_b_kernel(const float* __restrict__ B) {
    int row = blockIdx.x, t = threadIdx.x;
    float v = B[row * D_DIM + t];
    g_Bbf[row * D_DIM + t] = __float2bfloat16(v);
    float s = warp_sum(v * v);
    __shared__ float sm[4];
    if ((t & 31) == 0) sm[t >> 5] = s;
    __syncthreads();
    if (t == 0) g_b2[row] = sm[0] + sm[1] + sm[2] + sm[3];
}

// ---------------------------------------------------------------------------
// Main: per block computes dens[n0..n0+127, m] for one cluster m.
// Tile: 128 (n) x 64 (q), K = 128 fully resident in SMEM.
// 8 warps: (wn 0..3) x (wq 0..1); each warp does a 32x32 sub-tile via
// mma.sync.m16n8k16 bf16 (2 m-tiles x 4 n-tiles x 8 k-steps).
// ---------------------------------------------------------------------------
__global__ void __launch_bounds__(256) kde_main_kernel(
    const float* __restrict__ A, const float* __restrict__ B,
    const float* __restrict__ var_ptr)
{
    extern __shared__ char smem_raw[];
    __nv_bfloat16* As = (__nv_bfloat16*)smem_raw;                         // 128 x SA
    __nv_bfloat16* Bs = (__nv_bfloat16*)(smem_raw + 128 * SA * 2);        // 64 x SB
    float* sdens      = (float*)(smem_raw + 128 * SA * 2 + 64 * SB * 2);  // 128 x 2

    const int tid  = threadIdx.x;
    const int lane = tid & 31, warp = tid >> 5;
    const int wn = warp >> 1, wq = warp & 1;
    const int g = lane >> 2, tig = lane & 3;
    const int n0 = blockIdx.x * 128;
    const int m  = blockIdx.y;

    // Load tiles (bf16, coalesced uint4)
    {
        const uint4* srcA = (const uint4*)(g_Abf + (size_t)n0 * D_DIM);
#pragma unroll
        for (int i = 0; i < 8; i++) {
            int idx = tid + i * 256;            // 0..2047
            int r = idx >> 4, c = idx & 15;
            *((uint4*)(As + r * SA) + c) = srcA[r * 16 + c];
        }
        const uint4* srcB = (const uint4*)(g_Bbf + (size_t)m * Q_PTS * D_DIM);
#pragma unroll
        for (int i = 0; i < 4; i++) {
            int idx = tid + i * 256;            // 0..1023
            int r = idx >> 4, c = idx & 15;
            *((uint4*)(Bs + r * SB) + c) = srcB[r * 16 + c];
        }
    }
    __syncthreads();

    float c[2][4][4];
#pragma unroll
    for (int mt = 0; mt < 2; mt++)
#pragma unroll
        for (int nt = 0; nt < 4; nt++)
#pragma unroll
            for (int i = 0; i < 4; i++) c[mt][nt][i] = 0.0f;

#pragma unroll
    for (int ks = 0; ks < 8; ks++) {
        const int kb = ks * 16 + tig * 2;
        uint32_t a[2][4];
#pragma unroll
        for (int mt = 0; mt < 2; mt++) {
            int r = wn * 32 + mt * 16 + g;
            const __nv_bfloat16* pr0 = As + r * SA;
            const __nv_bfloat16* pr1 = As + (r + 8) * SA;
            a[mt][0] = *(const uint32_t*)(pr0 + kb);
            a[mt][1] = *(const uint32_t*)(pr1 + kb);
            a[mt][2] = *(const uint32_t*)(pr0 + kb + 8);
            a[mt][3] = *(const uint32_t*)(pr1 + kb + 8);
        }
#pragma unroll
        for (int nt = 0; nt < 4; nt++) {
            int col = wq * 32 + nt * 8 + g;
            const __nv_bfloat16* pc = Bs + col * SB;
            uint32_t b0 = *(const uint32_t*)(pc + kb);
            uint32_t b1 = *(const uint32_t*)(pc + kb + 8);
#pragma unroll
            for (int mt = 0; mt < 2; mt++) {
                asm volatile(
                    "mma.sync.aligned.m16n8k16.row.col.f32.bf16.bf16.f32 "
                    "{%0,%1,%2,%3}, {%4,%5,%6,%7}, {%8,%9}, {%0,%1,%2,%3};\n"
                    : "+f"(c[mt][nt][0]), "+f"(c[mt][nt][1]),
                      "+f"(c[mt][nt][2]), "+f"(c[mt][nt][3])
                    : "r"(a[mt][0]), "r"(a[mt][1]), "r"(a[mt][2]), "r"(a[mt][3]),
                      "r"(b0), "r"(b1));
            }
        }
    }

    // Epilogue: exponent screen + (rare) exact fp32 recompute, sum over q.
    const float inv_var = 1.0f / var_ptr[0];

    float a2v[2][2];
#pragma unroll
    for (int mt = 0; mt < 2; mt++)
#pragma unroll
        for (int rs = 0; rs < 2; rs++)
            a2v[mt][rs] = g_a2[n0 + wn * 32 + mt * 16 + rs * 8 + g];

    float b2v[4][2];
#pragma unroll
    for (int nt = 0; nt < 4; nt++)
#pragma unroll
        for (int u = 0; u < 2; u++)
            b2v[nt][u] = g_b2[m * Q_PTS + wq * 32 + nt * 8 + tig * 2 + u];

    float acc[2][2] = {{0.0f, 0.0f}, {0.0f, 0.0f}};
#pragma unroll
    for (int mt = 0; mt < 2; mt++) {
#pragma unroll
        for (int nt = 0; nt < 4; nt++) {
#pragma unroll
            for (int rs = 0; rs < 2; rs++) {
#pragma unroll
                for (int u = 0; u < 2; u++) {
                    // c regs: [0]=(g,2t) [1]=(g,2t+1) [2]=(g+8,2t) [3]=(g+8,2t+1)
                    float ab = c[mt][nt][rs * 2 + u];
                    float e  = -0.5f * inv_var * (a2v[mt][rs] - 2.0f * ab + b2v[nt][u]);
                    float contrib = 0.0f;
                    if (e > -115.0f) {   // bf16 screen margin >> worst-case error
                        int n_glob = n0 + wn * 32 + mt * 16 + rs * 8 + g;
                        int mq = m * Q_PTS + wq * 32 + nt * 8 + tig * 2 + u;
                        const float* ar = A + (size_t)n_glob * D_DIM;
                        const float* br = B + (size_t)mq * D_DIM;
                        float dot = 0.0f;
                        for (int k = 0; k < D_DIM; k++) dot = fmaf(ar[k], br[k], dot);
                        float ee = -0.5f * inv_var * (a2v[mt][rs] - 2.0f * dot + b2v[nt][u]);
                        contrib = expf(ee);
                    }
                    acc[mt][rs] += contrib;
                }
            }
        }
    }

    // Reduce the q-partials: lanes tig 0..3 share the same row.
#pragma unroll
    for (int mt = 0; mt < 2; mt++) {
#pragma unroll
        for (int rs = 0; rs < 2; rs++) {
            float v = acc[mt][rs];
            v += __shfl_xor_sync(0xffffffffu, v, 1);
            v += __shfl_xor_sync(0xffffffffu, v, 2);
            if (tig == 0)
                sdens[(wn * 32 + mt * 16 + rs * 8 + g) * 2 + wq] = v;
        }
    }
    __syncthreads();
    if (tid < 128) {
        float d = sdens[tid * 2 + 0] + sdens[tid * 2 + 1];
        g_dens[(size_t)(n0 + tid) * M_CL + m] = d;
    }
}

// ---------------------------------------------------------------------------
// Normalize: prob[n,m] = dens[n,m] / (sum_m dens + 1e-10)
// ---------------------------------------------------------------------------
__global__ void norm_kernel(float* __restrict__ out) {
    int n = blockIdx.x, t = threadIdx.x;   // 128 threads = M
    float d = g_dens[(size_t)n * M_CL + t];
    float s = warp_sum(d);
    __shared__ float sm[4];
    if ((t & 31) == 0) sm[t >> 5] = s;
    __syncthreads();
    float tot = sm[0] + sm[1] + sm[2] + sm[3];
    out[(size_t)n * M_CL + t] = d / (tot + 1e-10f);
}

// ---------------------------------------------------------------------------
extern "C" void kernel_launch(void* const* d_in, const int* in_sizes, int n_in,
                              void* d_out, int out_size) {
    const float* A   = (const float*)d_in[0];   // [4096,128]
    const float* B   = (const float*)d_in[1];   // [128,64,128]
    const float* var = (const float*)d_in[2];   // [1]
    float* out = (float*)d_out;                 // [4096,128]

    const size_t smem = 128 * SA * 2 + 64 * SB * 2 + 128 * 2 * sizeof(float);
    cudaFuncSetAttribute(kde_main_kernel,
                         cudaFuncAttributeMaxDynamicSharedMemorySize, (int)smem);

    prep_a_kernel<<<N_ROWS, 128>>>(A);
    prep_b_kernel<<<MQ, 128>>>(B);

    dim3 grid(N_ROWS / 128, M_CL);
    kde_main_kernel<<<grid, 256, smem>>>(A, B, var);

    norm_kernel<<<N_ROWS, 128>>>(out);
}